// round 11
// baseline (speedup 1.0000x reference)
#include <cuda_runtime.h>
#include <cuda_bf16.h>
#include <math.h>
#include <cstdint>

#define NAGT 1024
#define RNN  128
#define NMIX 20

typedef unsigned long long ull;
typedef unsigned int uint;

// ---------------- device scratch ----------------
__device__ float g_xin[NAGT * 128];          // [emb(64) | pool(64)]
__device__ float g_Hs[NAGT * 4096];          // Hs[m][g*64+e], 16 MB
__device__ float g_gatesA[NAGT * 512];       // xin @ W_ih^T
__device__ float g_gatesB[NAGT * 512];       // h0  @ W_hh^T

// ================= bf16-split helpers ====================================
__device__ __forceinline__ uint pack_hi2(float x, float y, float& lx, float& ly) {
    __nv_bfloat16 hx = __float2bfloat16(x);
    __nv_bfloat16 hy = __float2bfloat16(y);
    lx = x - __bfloat162float(hx);
    ly = y - __bfloat162float(hy);
    __nv_bfloat162 h; h.x = hx; h.y = hy;
    return *(uint*)&h;
}
__device__ __forceinline__ uint pack2(float x, float y) {
    __nv_bfloat162 h; h.x = __float2bfloat16(x); h.y = __float2bfloat16(y);
    return *(uint*)&h;
}
__device__ __forceinline__ void mma16816(float* d, uint a0, uint a1, uint a2, uint a3,
                                         uint b0, uint b1) {
    asm volatile(
        "mma.sync.aligned.m16n8k16.row.col.f32.bf16.bf16.f32 "
        "{%0,%1,%2,%3}, {%4,%5,%6,%7}, {%8,%9}, {%0,%1,%2,%3};"
        : "+f"(d[0]), "+f"(d[1]), "+f"(d[2]), "+f"(d[3])
        : "r"(a0), "r"(a1), "r"(a2), "r"(a3), "r"(b0), "r"(b1));
}

// ---------------- FFMA2 helpers ----------------
__device__ __forceinline__ void ffma2(ull& d, ull a, ull b) {
    asm("fma.rn.f32x2 %0, %1, %2, %0;" : "+l"(d) : "l"(a), "l"(b));
}
__device__ __forceinline__ float2 unpack2(ull v) {
    float2 r;
    asm("mov.b64 {%0,%1}, %2;" : "=f"(r.x), "=f"(r.y) : "l"(v));
    return r;
}
__device__ __forceinline__ ull dup2(float x) {
    ull r;
    asm("mov.b64 %0, {%1,%1};" : "=l"(r) : "f"(x));
    return r;
}

// ---------------- MUFU.TANH-based nonlinearities ----------------
__device__ __forceinline__ float tanh_ap(float x) {
    float y;
    asm("tanh.approx.f32 %0, %1;" : "=f"(y) : "f"(x));
    return y;
}
__device__ __forceinline__ float sigmoid_ap(float x) {
    return fmaf(tanh_ap(0.5f * x), 0.5f, 0.5f);
}

// ================= Kernel A: hs (tensor) + gatesB (ffma2) ================
#define HS_AROW 272
#define HS_A_HI 0
#define HS_A_LO (128 * HS_AROW)
#define HS_B_HI (2 * 128 * HS_AROW)
#define HS_B_LO (HS_B_HI + 256 * HS_AROW)
#define HS_SMEM (HS_B_LO + 256 * HS_AROW)   // 208896

struct GSmem {
    float As[64 * 66];
    float Bs[32 * 130];
};

__global__ void __launch_bounds__(512) kA(const float* __restrict__ h0,
                                          const float* __restrict__ Wsoc,
                                          const float* __restrict__ Whh) {
    extern __shared__ __align__(16) char sm[];
    const int tid = threadIdx.x;

    if (blockIdx.x < 128) {
        const int wid = tid >> 5, lane = tid & 31;
        const int m0 = (blockIdx.x & 7) * 128;
        const int c0 = (blockIdx.x >> 3) * 256;

#pragma unroll
        for (int p = 0; p < 8; p++) {
            int idx = tid + p * 512;
            int r = idx >> 5, c4 = idx & 31;
            float4 v = *(const float4*)(h0 + (m0 + r) * 128 + c4 * 4);
            float lx, ly, lz, lw;
            uint2 H, L;
            H.x = pack_hi2(v.x, v.y, lx, ly);
            H.y = pack_hi2(v.z, v.w, lz, lw);
            L.x = pack2(lx, ly);
            L.y = pack2(lz, lw);
            int off = r * HS_AROW + c4 * 8;
            *(uint2*)(sm + HS_A_HI + off) = H;
            *(uint2*)(sm + HS_A_LO + off) = L;
        }
#pragma unroll
        for (int p = 0; p < 16; p++) {
            int idx = tid + p * 512;
            int r = idx >> 5, c4 = idx & 31;
            int gc = c0 + r;
            float4 v = *(const float4*)(Wsoc + (gc & 63) * 8192 + (gc >> 6) * 128 + c4 * 4);
            float lx, ly, lz, lw;
            uint2 H, L;
            H.x = pack_hi2(v.x, v.y, lx, ly);
            H.y = pack_hi2(v.z, v.w, lz, lw);
            L.x = pack2(lx, ly);
            L.y = pack2(lz, lw);
            int off = r * HS_AROW + c4 * 8;
            *(uint2*)(sm + HS_B_HI + off) = H;
            *(uint2*)(sm + HS_B_LO + off) = L;
        }
        __syncthreads();

        const int wm = (wid >> 2) * 32;
        const int wn = (wid & 3) * 64;
        const int tq = lane >> 2;
        const int tr = lane & 3;

        float acc[2][8][4];
#pragma unroll
        for (int i = 0; i < 2; i++)
#pragma unroll
            for (int j = 0; j < 8; j++)
#pragma unroll
                for (int q = 0; q < 4; q++) acc[i][j][q] = 0.0f;

#pragma unroll 1
        for (int ks = 0; ks < 8; ks++) {
            const int kb = ks * 32 + tr * 4;
            uint aH[2][4], aL[2][4];
#pragma unroll
            for (int mf = 0; mf < 2; mf++) {
                int row = wm + mf * 16 + tq;
                int o0 = row * HS_AROW + kb;
                int o1 = o0 + 8 * HS_AROW;
                aH[mf][0] = *(const uint*)(sm + HS_A_HI + o0);
                aH[mf][1] = *(const uint*)(sm + HS_A_HI + o1);
                aH[mf][2] = *(const uint*)(sm + HS_A_HI + o0 + 16);
                aH[mf][3] = *(const uint*)(sm + HS_A_HI + o1 + 16);
                aL[mf][0] = *(const uint*)(sm + HS_A_LO + o0);
                aL[mf][1] = *(const uint*)(sm + HS_A_LO + o1);
                aL[mf][2] = *(const uint*)(sm + HS_A_LO + o0 + 16);
                aL[mf][3] = *(const uint*)(sm + HS_A_LO + o1 + 16);
            }
#pragma unroll
            for (int nf = 0; nf < 8; nf++) {
                int col = wn + nf * 8 + tq;
                int o0 = col * HS_AROW + kb;
                uint bH0 = *(const uint*)(sm + HS_B_HI + o0);
                uint bH1 = *(const uint*)(sm + HS_B_HI + o0 + 16);
                uint bL0 = *(const uint*)(sm + HS_B_LO + o0);
                uint bL1 = *(const uint*)(sm + HS_B_LO + o0 + 16);
#pragma unroll
                for (int mf = 0; mf < 2; mf++) {
                    mma16816(acc[mf][nf], aH[mf][0], aH[mf][1], aH[mf][2], aH[mf][3], bH0, bH1);
                    mma16816(acc[mf][nf], aH[mf][0], aH[mf][1], aH[mf][2], aH[mf][3], bL0, bL1);
                    mma16816(acc[mf][nf], aL[mf][0], aL[mf][1], aL[mf][2], aL[mf][3], bH0, bH1);
                }
            }
        }
#pragma unroll
        for (int mf = 0; mf < 2; mf++) {
            int row0 = m0 + wm + mf * 16 + tq;
#pragma unroll
            for (int nf = 0; nf < 8; nf++) {
                int col = c0 + wn + nf * 8 + tr * 2;
                *(float2*)&g_Hs[row0 * 4096 + col] =
                    make_float2(acc[mf][nf][0], acc[mf][nf][1]);
                *(float2*)&g_Hs[(row0 + 8) * 4096 + col] =
                    make_float2(acc[mf][nf][2], acc[mf][nf][3]);
            }
        }
    } else {
        // ---------------- gatesB: h0 @ Whh^T, 64m x 128n, 512 thr -------
        GSmem& s = *(GSmem*)sm;
        const int b = blockIdx.x - 128;
        const int m0 = (b & 15) * 64;
        const int j0 = (b >> 4) * 128;
        const int tx = tid & 15, ty = tid >> 4;   // ty 0..31

        ull acc[2][4];
#pragma unroll
        for (int i = 0; i < 2; i++)
#pragma unroll
            for (int j = 0; j < 4; j++) acc[i][j] = 0ull;

#pragma unroll 1
        for (int kc = 0; kc < 4; kc++) {
            const int kb = kc * 32;
            {
                int k4 = tid & 7, m = tid >> 3;
                float4 v = *(const float4*)(h0 + (m0 + m) * 128 + kb + k4 * 4);
                int base = m * 66 + k4 * 8;
                *(ull*)&s.As[base + 0] = dup2(v.x);
                *(ull*)&s.As[base + 2] = dup2(v.y);
                *(ull*)&s.As[base + 4] = dup2(v.z);
                *(ull*)&s.As[base + 6] = dup2(v.w);
            }
#pragma unroll
            for (int p = 0; p < 2; p++) {
                int idx = tid + p * 512;
                int k4 = idx & 7, c = idx >> 3;
                float4 v = *(const float4*)(Whh + (j0 + c) * 128 + kb + k4 * 4);
                s.Bs[(k4 * 4 + 0) * 130 + c] = v.x;
                s.Bs[(k4 * 4 + 1) * 130 + c] = v.y;
                s.Bs[(k4 * 4 + 2) * 130 + c] = v.z;
                s.Bs[(k4 * 4 + 3) * 130 + c] = v.w;
            }
            __syncthreads();
#pragma unroll 4
            for (int k = 0; k < 32; k++) {
                ull bb[4];
#pragma unroll
                for (int j = 0; j < 4; j++)
                    bb[j] = *(const ull*)&s.Bs[k * 130 + 2 * tx + 32 * j];
#pragma unroll
                for (int i = 0; i < 2; i++) {
                    ull a = *(const ull*)&s.As[(ty * 2 + i) * 66 + 2 * k];
#pragma unroll
                    for (int j = 0; j < 4; j++) ffma2(acc[i][j], a, bb[j]);
                }
            }
            __syncthreads();
        }
#pragma unroll
        for (int i = 0; i < 2; i++) {
            int m = m0 + ty * 2 + i;
#pragma unroll
            for (int j = 0; j < 4; j++) {
                float2 v = unpack2(acc[i][j]);
                *(float2*)&g_gatesB[m * 512 + j0 + 2 * tx + 32 * j] = v;
            }
        }
    }
}

// ---------------- K3: pool (+ fused emb), grid=1024 ----------------------
// phase2: 8 independent warps, each gathers the list it built, float2 lanes
__global__ void __launch_bounds__(256) k_pool(const float* __restrict__ xabs,
                                              const float* __restrict__ b_soc,
                                              const float* __restrict__ xoff,
                                              const float* __restrict__ W_emb,
                                              const float* __restrict__ b_emb) {
    __shared__ float sx[NAGT];
    __shared__ float sy[NAGT];
    __shared__ unsigned short list[NAGT];
    __shared__ float red[8][64];
    const int n = blockIdx.x;
    const int tid = threadIdx.x;

    if (tid < 64) {
        float v = b_emb[tid];
        v = fmaf(xoff[2 * n + 0], W_emb[2 * tid + 0], v);
        v = fmaf(xoff[2 * n + 1], W_emb[2 * tid + 1], v);
        g_xin[n * 128 + tid] = fmaxf(v, 0.0f);
    }
    for (int i = tid; i < NAGT; i += 256) {
        float2 p = *(const float2*)(xabs + 2 * i);
        sx[i] = p.x; sy[i] = p.y;
    }
    __syncthreads();

    const float xn = sx[n] - 0.2f;
    const float yn = sy[n] - 0.2f;
    const int lane = tid & 31, w = tid >> 5;

    // phase 1: ballot-compacted per-warp neighbor list (segment w: 128 m's)
    unsigned cnt = 0;
#pragma unroll
    for (int t = 0; t < 4; t++) {
        int m = w * 128 + t * 32 + lane;
        float dx = sx[m] - xn;
        float dy = sy[m] - yn;
        bool v = (m != n) && dx >= 0.0f && dx < 0.4f && dy >= 0.0f && dy < 0.4f;
        int cell = 0;
        if (v) {
            int cx = (int)floorf(dx * 20.0f);
            int cy = (int)floorf(dy * 20.0f);
            v = (cx >= 0) && (cx < 8) && (cy >= 0) && (cy < 8);
            cell = cx + cy * 8;
        }
        unsigned mask = __ballot_sync(0xffffffffu, v);
        if (v) {
            int pos = cnt + __popc(mask & ((1u << lane) - 1u));
            list[w * 128 + pos] = (unsigned short)((m << 6) | cell);
        }
        cnt += __popc(mask);
    }
    // no cross-warp sync needed before phase2: each warp reads only its list

    // phase 2: warp w walks its own cnt entries; lane loads float2 (e=2*lane)
    float2 accA = make_float2(0.0f, 0.0f);
    float2 accB = make_float2(0.0f, 0.0f);
    int i = 0;
    for (; i + 1 < (int)cnt; i += 2) {
        unsigned v0 = list[w * 128 + i];
        unsigned v1 = list[w * 128 + i + 1];
        float2 t0 = *(const float2*)(g_Hs + (v0 >> 6) * 4096 + (v0 & 63) * 64 + lane * 2);
        float2 t1 = *(const float2*)(g_Hs + (v1 >> 6) * 4096 + (v1 & 63) * 64 + lane * 2);
        accA.x += t0.x; accA.y += t0.y;
        accB.x += t1.x; accB.y += t1.y;
    }
    if (i < (int)cnt) {
        unsigned v0 = list[w * 128 + i];
        float2 t0 = *(const float2*)(g_Hs + (v0 >> 6) * 4096 + (v0 & 63) * 64 + lane * 2);
        accA.x += t0.x; accA.y += t0.y;
    }
    *(float2*)&red[w][lane * 2] = make_float2(accA.x + accB.x, accA.y + accB.y);
    __syncthreads();

    if (tid < 64) {
        float sum = b_soc[tid];
#pragma unroll
        for (int q = 0; q < 8; q++) sum += red[q][tid];
        g_xin[n * 128 + 64 + tid] = fmaxf(sum, 0.0f);
    }
}

// ---------------- gatesA: xin @ Wih^T, grid=(16,4), 256 thr --------------
__global__ void __launch_bounds__(256) k_gatesA(const float* __restrict__ Wih) {
    __shared__ __align__(16) GSmem s;
    const int m0 = blockIdx.x * 64;
    const int j0 = blockIdx.y * 128;
    const int tid = threadIdx.x;
    const int tx = tid & 15, ty = tid >> 4;

    const float* Bw = Wih + j0 * 128;

    ull acc[4][4];
#pragma unroll
    for (int i = 0; i < 4; i++)
#pragma unroll
        for (int j = 0; j < 4; j++) acc[i][j] = 0ull;

#pragma unroll 1
    for (int kc = 0; kc < 4; kc++) {
        const int kb = kc * 32;
#pragma unroll
        for (int p = 0; p < 2; p++) {
            int idx = tid + p * 256;
            int k4 = idx & 7, m = idx >> 3;
            float4 v = *(const float4*)(g_xin + (m0 + m) * 128 + kb + k4 * 4);
            int base = m * 66 + k4 * 8;
            *(ull*)&s.As[base + 0] = dup2(v.x);
            *(ull*)&s.As[base + 2] = dup2(v.y);
            *(ull*)&s.As[base + 4] = dup2(v.z);
            *(ull*)&s.As[base + 6] = dup2(v.w);
        }
#pragma unroll
        for (int p = 0; p < 4; p++) {
            int idx = tid + p * 256;
            int k4 = idx & 7, c = idx >> 3;
            float4 v = *(const float4*)(Bw + c * 128 + kb + k4 * 4);
            s.Bs[(k4 * 4 + 0) * 130 + c] = v.x;
            s.Bs[(k4 * 4 + 1) * 130 + c] = v.y;
            s.Bs[(k4 * 4 + 2) * 130 + c] = v.z;
            s.Bs[(k4 * 4 + 3) * 130 + c] = v.w;
        }
        __syncthreads();
#pragma unroll 4
        for (int k = 0; k < 32; k++) {
            ull bb[4];
#pragma unroll
            for (int j = 0; j < 4; j++)
                bb[j] = *(const ull*)&s.Bs[k * 130 + 2 * tx + 32 * j];
#pragma unroll
            for (int i = 0; i < 4; i++) {
                ull a = *(const ull*)&s.As[(ty * 4 + i) * 66 + 2 * k];
#pragma unroll
                for (int j = 0; j < 4; j++) ffma2(acc[i][j], a, bb[j]);
            }
        }
        __syncthreads();
    }
#pragma unroll
    for (int i = 0; i < 4; i++) {
        int m = m0 + ty * 4 + i;
#pragma unroll
        for (int j = 0; j < 4; j++) {
            float2 v = unpack2(acc[i][j]);
            *(float2*)&g_gatesA[m * 512 + j0 + 2 * tx + 32 * j] = v;
        }
    }
}

// ---------------- Kernel D: fused LSTM elementwise + out GEMM ------------
// grid=128 (8 rows), 256 threads. GEMM thread = (1 col, 4 rows) with
// float4 broadcast a-loads: 2 crossbar wavefronts/k/warp (was 3, 16 warps).
#define KD_WOT_PAD 121
#define KD_SMEM ((8 * 128 + 128 * KD_WOT_PAD) * 4)   // 66048 B

__global__ void __launch_bounds__(256) kD(const float* __restrict__ c0v,
                                          const float* __restrict__ b_ih,
                                          const float* __restrict__ b_hh,
                                          const float* __restrict__ Wout,
                                          const float* __restrict__ b_out,
                                          float* __restrict__ out) {
    extern __shared__ float sdynf[];
    float* Hn  = sdynf;                 // [8][128]
    float* WoT = sdynf + 8 * 128;       // [128][121]
    const int m0 = blockIdx.x * 8;
    const int tid = threadIdx.x;

    // ---- LSTM elementwise into smem (1024 el, 4/thread) ----
#pragma unroll
    for (int p = 0; p < 4; p++) {
        int id = tid + p * 256;
        int r = id >> 7, k = id & 127;
        const float* ga = g_gatesA + (m0 + r) * 512;
        const float* gb = g_gatesB + (m0 + r) * 512;
        float iv = ga[k]       + gb[k]       + b_ih[k]       + b_hh[k];
        float fv = ga[128 + k] + gb[128 + k] + b_ih[128 + k] + b_hh[128 + k];
        float gv = ga[256 + k] + gb[256 + k] + b_ih[256 + k] + b_hh[256 + k];
        float ov = ga[384 + k] + gb[384 + k] + b_ih[384 + k] + b_hh[384 + k];
        float si = sigmoid_ap(iv);
        float sf = sigmoid_ap(fv);
        float so = sigmoid_ap(ov);
        float c  = sf * c0v[(m0 + r) * 128 + k] + si * tanh_ap(gv);
        Hn[r * 128 + k] = so * tanh_ap(c);
    }

    // ---- load Wout transposed: WoT[k][c] (3840 float4 = 15 rounds) ----
#pragma unroll
    for (int p = 0; p < 15; p++) {
        int i = tid + p * 256;
        int c = i >> 5, k4 = i & 31;
        float4 v = *(const float4*)(Wout + c * 128 + k4 * 4);
        WoT[(k4 * 4 + 0) * KD_WOT_PAD + c] = v.x;
        WoT[(k4 * 4 + 1) * KD_WOT_PAD + c] = v.y;
        WoT[(k4 * 4 + 2) * KD_WOT_PAD + c] = v.z;
        WoT[(k4 * 4 + 3) * KD_WOT_PAD + c] = v.w;
    }
    __syncthreads();

    // ---- out GEMM: thread = (col tx, rows ty*4 .. ty*4+3) ----
    const int ty = tid >> 7;            // 0..1
    const int tx = tid & 127;           // col (active < 120)
    if (tx < 120) {
        const float* r0 = Hn + (ty * 4 + 0) * 128;
        const float* r1 = Hn + (ty * 4 + 1) * 128;
        const float* r2 = Hn + (ty * 4 + 2) * 128;
        const float* r3 = Hn + (ty * 4 + 3) * 128;
        float acc0 = 0.0f, acc1 = 0.0f, acc2 = 0.0f, acc3 = 0.0f;
#pragma unroll 4
        for (int k4 = 0; k4 < 32; k4++) {
            float4 a0 = *(const float4*)(r0 + k4 * 4);
            float4 a1 = *(const float4*)(r1 + k4 * 4);
            float4 a2 = *(const float4*)(r2 + k4 * 4);
            float4 a3 = *(const float4*)(r3 + k4 * 4);
            float b0 = WoT[(k4 * 4 + 0) * KD_WOT_PAD + tx];
            float b1 = WoT[(k4 * 4 + 1) * KD_WOT_PAD + tx];
            float b2 = WoT[(k4 * 4 + 2) * KD_WOT_PAD + tx];
            float b3 = WoT[(k4 * 4 + 3) * KD_WOT_PAD + tx];
            acc0 = fmaf(a0.x, b0, acc0); acc0 = fmaf(a0.y, b1, acc0);
            acc0 = fmaf(a0.z, b2, acc0); acc0 = fmaf(a0.w, b3, acc0);
            acc1 = fmaf(a1.x, b0, acc1); acc1 = fmaf(a1.y, b1, acc1);
            acc1 = fmaf(a1.z, b2, acc1); acc1 = fmaf(a1.w, b3, acc1);
            acc2 = fmaf(a2.x, b0, acc2); acc2 = fmaf(a2.y, b1, acc2);
            acc2 = fmaf(a2.z, b2, acc2); acc2 = fmaf(a2.w, b3, acc2);
            acc3 = fmaf(a3.x, b0, acc3); acc3 = fmaf(a3.y, b1, acc3);
            acc3 = fmaf(a3.z, b2, acc3); acc3 = fmaf(a3.w, b3, acc3);
        }
        float bo = b_out[tx];
        int cdiv = tx / 20, cmod = tx % 20;
        int base = cdiv * (NAGT * NMIX) + cmod;
        int n0 = m0 + ty * 4;
        out[base + (n0 + 0) * NMIX] = acc0 + bo;
        out[base + (n0 + 1) * NMIX] = acc1 + bo;
        out[base + (n0 + 2) * NMIX] = acc2 + bo;
        out[base + (n0 + 3) * NMIX] = acc3 + bo;
    }
}

// ---------------- launch ----------------
extern "C" void kernel_launch(void* const* d_in, const int* in_sizes, int n_in,
                              void* d_out, int out_size) {
    const float* xoff  = (const float*)d_in[0];
    const float* xabs  = (const float*)d_in[1];
    const float* h0    = (const float*)d_in[2];
    const float* c0    = (const float*)d_in[3];
    const float* W_emb = (const float*)d_in[4];
    const float* b_emb = (const float*)d_in[5];
    const float* W_soc = (const float*)d_in[6];
    const float* b_soc = (const float*)d_in[7];
    const float* W_ih  = (const float*)d_in[8];
    const float* W_hh  = (const float*)d_in[9];
    const float* b_ih  = (const float*)d_in[10];
    const float* b_hh  = (const float*)d_in[11];
    const float* W_out = (const float*)d_in[12];
    const float* b_out = (const float*)d_in[13];
    float* out = (float*)d_out;

    cudaFuncSetAttribute(kA, cudaFuncAttributeMaxDynamicSharedMemorySize, HS_SMEM);
    cudaFuncSetAttribute(kD, cudaFuncAttributeMaxDynamicSharedMemorySize, KD_SMEM);

    kA<<<192, 512, HS_SMEM>>>(h0, W_soc, W_hh);
    k_pool<<<NAGT, 256>>>(xabs, b_soc, xoff, W_emb, b_emb);
    k_gatesA<<<dim3(16, 4), 256>>>(W_ih);
    kD<<<128, 256, KD_SMEM>>>(c0, b_ih, b_hh, W_out, b_out, out);
}

// round 12
// speedup vs baseline: 1.2654x; 1.2654x over previous
#include <cuda_runtime.h>
#include <cuda_bf16.h>
#include <math.h>
#include <cstdint>

#define NAGT 1024
#define RNN  128
#define NMIX 20

typedef unsigned long long ull;
typedef unsigned int uint;

// ---------------- device scratch ----------------
__device__ float g_xin[NAGT * 128];          // [emb(64) | pool(64)]
__device__ float g_Hs[NAGT * 4096];          // Hs[m][g*64+e], 16 MB
__device__ float g_gatesA[NAGT * 512];       // xin @ W_ih^T
__device__ float g_gatesB[NAGT * 512];       // h0  @ W_hh^T

// ================= bf16-split helpers ====================================
__device__ __forceinline__ uint pack_hi2(float x, float y, float& lx, float& ly) {
    __nv_bfloat16 hx = __float2bfloat16(x);
    __nv_bfloat16 hy = __float2bfloat16(y);
    lx = x - __bfloat162float(hx);
    ly = y - __bfloat162float(hy);
    __nv_bfloat162 h; h.x = hx; h.y = hy;
    return *(uint*)&h;
}
__device__ __forceinline__ uint pack2(float x, float y) {
    __nv_bfloat162 h; h.x = __float2bfloat16(x); h.y = __float2bfloat16(y);
    return *(uint*)&h;
}
__device__ __forceinline__ void mma16816(float* d, uint a0, uint a1, uint a2, uint a3,
                                         uint b0, uint b1) {
    asm volatile(
        "mma.sync.aligned.m16n8k16.row.col.f32.bf16.bf16.f32 "
        "{%0,%1,%2,%3}, {%4,%5,%6,%7}, {%8,%9}, {%0,%1,%2,%3};"
        : "+f"(d[0]), "+f"(d[1]), "+f"(d[2]), "+f"(d[3])
        : "r"(a0), "r"(a1), "r"(a2), "r"(a3), "r"(b0), "r"(b1));
}

// ---------------- FFMA2 helpers (gatesA kernel) ----------------
__device__ __forceinline__ void ffma2(ull& d, ull a, ull b) {
    asm("fma.rn.f32x2 %0, %1, %2, %0;" : "+l"(d) : "l"(a), "l"(b));
}
__device__ __forceinline__ float2 unpack2(ull v) {
    float2 r;
    asm("mov.b64 {%0,%1}, %2;" : "=f"(r.x), "=f"(r.y) : "l"(v));
    return r;
}
__device__ __forceinline__ ull dup2(float x) {
    ull r;
    asm("mov.b64 %0, {%1,%1};" : "=l"(r) : "f"(x));
    return r;
}

// ---------------- MUFU.TANH-based nonlinearities ----------------
__device__ __forceinline__ float tanh_ap(float x) {
    float y;
    asm("tanh.approx.f32 %0, %1;" : "=f"(y) : "f"(x));
    return y;
}
__device__ __forceinline__ float sigmoid_ap(float x) {
    return fmaf(tanh_ap(0.5f * x), 0.5f, 0.5f);
}

// ================= Kernel A: hs tile (tensor) + gatesB slice (tensor) ====
// grid = 128 blocks: (m-tile = bx&7, c-tile = bx>>3).
// Phase 1: Hs tile 128m x 256n (bf16-split mma.sync, K=128 resident).
// Phase 2: gatesB slice 128m x 32n (j0 = (bx>>3)*32) reusing the A tiles.
#define HS_AROW 272
#define HS_A_HI 0
#define HS_A_LO (128 * HS_AROW)
#define HS_B_HI (2 * 128 * HS_AROW)
#define HS_B_LO (HS_B_HI + 256 * HS_AROW)
#define HS_SMEM (HS_B_LO + 256 * HS_AROW)   // 208896

struct GSmem {
    float As[64 * 66];
    float Bs[32 * 130];
};

__global__ void __launch_bounds__(512) kA(const float* __restrict__ h0,
                                          const float* __restrict__ Wsoc,
                                          const float* __restrict__ Whh) {
    extern __shared__ __align__(16) char sm[];
    const int tid = threadIdx.x;
    const int wid = tid >> 5, lane = tid & 31;
    const int m0 = (blockIdx.x & 7) * 128;
    const int c0 = (blockIdx.x >> 3) * 256;

    // ---- fill A: h0 tile 128 x 128 -> bf16 hi/lo ----
#pragma unroll
    for (int p = 0; p < 8; p++) {
        int idx = tid + p * 512;
        int r = idx >> 5, c4 = idx & 31;
        float4 v = *(const float4*)(h0 + (m0 + r) * 128 + c4 * 4);
        float lx, ly, lz, lw;
        uint2 H, L;
        H.x = pack_hi2(v.x, v.y, lx, ly);
        H.y = pack_hi2(v.z, v.w, lz, lw);
        L.x = pack2(lx, ly);
        L.y = pack2(lz, lw);
        int off = r * HS_AROW + c4 * 8;
        *(uint2*)(sm + HS_A_HI + off) = H;
        *(uint2*)(sm + HS_A_LO + off) = L;
    }
    // ---- fill B: Wsoc-derived 256 x 128 ----
#pragma unroll
    for (int p = 0; p < 16; p++) {
        int idx = tid + p * 512;
        int r = idx >> 5, c4 = idx & 31;
        int gc = c0 + r;
        float4 v = *(const float4*)(Wsoc + (gc & 63) * 8192 + (gc >> 6) * 128 + c4 * 4);
        float lx, ly, lz, lw;
        uint2 H, L;
        H.x = pack_hi2(v.x, v.y, lx, ly);
        H.y = pack_hi2(v.z, v.w, lz, lw);
        L.x = pack2(lx, ly);
        L.y = pack2(lz, lw);
        int off = r * HS_AROW + c4 * 8;
        *(uint2*)(sm + HS_B_HI + off) = H;
        *(uint2*)(sm + HS_B_LO + off) = L;
    }
    __syncthreads();

    const int wm = (wid >> 2) * 32;
    const int wn = (wid & 3) * 64;
    const int tq = lane >> 2;
    const int tr = lane & 3;

    {
        float acc[2][8][4];
#pragma unroll
        for (int i = 0; i < 2; i++)
#pragma unroll
            for (int j = 0; j < 8; j++)
#pragma unroll
                for (int q = 0; q < 4; q++) acc[i][j][q] = 0.0f;

#pragma unroll 1
        for (int ks = 0; ks < 8; ks++) {
            const int kb = ks * 32 + tr * 4;
            uint aH[2][4], aL[2][4];
#pragma unroll
            for (int mf = 0; mf < 2; mf++) {
                int row = wm + mf * 16 + tq;
                int o0 = row * HS_AROW + kb;
                int o1 = o0 + 8 * HS_AROW;
                aH[mf][0] = *(const uint*)(sm + HS_A_HI + o0);
                aH[mf][1] = *(const uint*)(sm + HS_A_HI + o1);
                aH[mf][2] = *(const uint*)(sm + HS_A_HI + o0 + 16);
                aH[mf][3] = *(const uint*)(sm + HS_A_HI + o1 + 16);
                aL[mf][0] = *(const uint*)(sm + HS_A_LO + o0);
                aL[mf][1] = *(const uint*)(sm + HS_A_LO + o1);
                aL[mf][2] = *(const uint*)(sm + HS_A_LO + o0 + 16);
                aL[mf][3] = *(const uint*)(sm + HS_A_LO + o1 + 16);
            }
#pragma unroll
            for (int nf = 0; nf < 8; nf++) {
                int col = wn + nf * 8 + tq;
                int o0 = col * HS_AROW + kb;
                uint bH0 = *(const uint*)(sm + HS_B_HI + o0);
                uint bH1 = *(const uint*)(sm + HS_B_HI + o0 + 16);
                uint bL0 = *(const uint*)(sm + HS_B_LO + o0);
                uint bL1 = *(const uint*)(sm + HS_B_LO + o0 + 16);
#pragma unroll
                for (int mf = 0; mf < 2; mf++) {
                    mma16816(acc[mf][nf], aH[mf][0], aH[mf][1], aH[mf][2], aH[mf][3], bH0, bH1);
                    mma16816(acc[mf][nf], aH[mf][0], aH[mf][1], aH[mf][2], aH[mf][3], bL0, bL1);
                    mma16816(acc[mf][nf], aL[mf][0], aL[mf][1], aL[mf][2], aL[mf][3], bH0, bH1);
                }
            }
        }
#pragma unroll
        for (int mf = 0; mf < 2; mf++) {
            int row0 = m0 + wm + mf * 16 + tq;
#pragma unroll
            for (int nf = 0; nf < 8; nf++) {
                int col = c0 + wn + nf * 8 + tr * 2;
                *(float2*)&g_Hs[row0 * 4096 + col] =
                    make_float2(acc[mf][nf][0], acc[mf][nf][1]);
                *(float2*)&g_Hs[(row0 + 8) * 4096 + col] =
                    make_float2(acc[mf][nf][2], acc[mf][nf][3]);
            }
        }
    }

    // ================= phase 2: gatesB slice 128m x 32n ==================
    __syncthreads();   // all warps done with Bs before overwrite
    const int j0 = (blockIdx.x >> 3) * 32;
    // convert Whh rows j0..j0+31 (K=128) into HS_B_HI/LO
#pragma unroll
    for (int p = 0; p < 2; p++) {
        int idx = tid + p * 512;            // 1024 float4 = 32 rows x 32 c4
        int r = idx >> 5, c4 = idx & 31;
        float4 v = *(const float4*)(Whh + (j0 + r) * 128 + c4 * 4);
        float lx, ly, lz, lw;
        uint2 H, L;
        H.x = pack_hi2(v.x, v.y, lx, ly);
        H.y = pack_hi2(v.z, v.w, lz, lw);
        L.x = pack2(lx, ly);
        L.y = pack2(lz, lw);
        int off = r * HS_AROW + c4 * 8;
        *(uint2*)(sm + HS_B_HI + off) = H;
        *(uint2*)(sm + HS_B_LO + off) = L;
    }
    __syncthreads();

    const int wn2 = (wid & 3) * 8;          // 8-col warp slice of the 32
    float acc2[2][4];
#pragma unroll
    for (int i = 0; i < 2; i++)
#pragma unroll
        for (int q = 0; q < 4; q++) acc2[i][q] = 0.0f;

#pragma unroll 1
    for (int ks = 0; ks < 8; ks++) {
        const int kb = ks * 32 + tr * 4;
        uint aH[2][4], aL[2][4];
#pragma unroll
        for (int mf = 0; mf < 2; mf++) {
            int row = wm + mf * 16 + tq;
            int o0 = row * HS_AROW + kb;
            int o1 = o0 + 8 * HS_AROW;
            aH[mf][0] = *(const uint*)(sm + HS_A_HI + o0);
            aH[mf][1] = *(const uint*)(sm + HS_A_HI + o1);
            aH[mf][2] = *(const uint*)(sm + HS_A_HI + o0 + 16);
            aH[mf][3] = *(const uint*)(sm + HS_A_HI + o1 + 16);
            aL[mf][0] = *(const uint*)(sm + HS_A_LO + o0);
            aL[mf][1] = *(const uint*)(sm + HS_A_LO + o1);
            aL[mf][2] = *(const uint*)(sm + HS_A_LO + o0 + 16);
            aL[mf][3] = *(const uint*)(sm + HS_A_LO + o1 + 16);
        }
        int col = wn2 + tq;
        int o0 = col * HS_AROW + kb;
        uint bH0 = *(const uint*)(sm + HS_B_HI + o0);
        uint bH1 = *(const uint*)(sm + HS_B_HI + o0 + 16);
        uint bL0 = *(const uint*)(sm + HS_B_LO + o0);
        uint bL1 = *(const uint*)(sm + HS_B_LO + o0 + 16);
#pragma unroll
        for (int mf = 0; mf < 2; mf++) {
            mma16816(acc2[mf], aH[mf][0], aH[mf][1], aH[mf][2], aH[mf][3], bH0, bH1);
            mma16816(acc2[mf], aH[mf][0], aH[mf][1], aH[mf][2], aH[mf][3], bL0, bL1);
            mma16816(acc2[mf], aL[mf][0], aL[mf][1], aL[mf][2], aL[mf][3], bH0, bH1);
        }
    }
#pragma unroll
    for (int mf = 0; mf < 2; mf++) {
        int row0 = m0 + wm + mf * 16 + tq;
        int col = j0 + wn2 + tr * 2;
        *(float2*)&g_gatesB[row0 * 512 + col] = make_float2(acc2[mf][0], acc2[mf][1]);
        *(float2*)&g_gatesB[(row0 + 8) * 512 + col] = make_float2(acc2[mf][2], acc2[mf][3]);
    }
}

// ---------------- K3: pool (+ fused emb), grid=1024 (r10 version) --------
__global__ void __launch_bounds__(256) k_pool(const float* __restrict__ xabs,
                                              const float* __restrict__ b_soc,
                                              const float* __restrict__ xoff,
                                              const float* __restrict__ W_emb,
                                              const float* __restrict__ b_emb) {
    __shared__ float sx[NAGT];
    __shared__ float sy[NAGT];
    __shared__ unsigned short list[NAGT];
    __shared__ unsigned s_cnt[8];
    __shared__ float red[4][64];
    const int n = blockIdx.x;
    const int tid = threadIdx.x;

    if (tid < 64) {
        float v = b_emb[tid];
        v = fmaf(xoff[2 * n + 0], W_emb[2 * tid + 0], v);
        v = fmaf(xoff[2 * n + 1], W_emb[2 * tid + 1], v);
        g_xin[n * 128 + tid] = fmaxf(v, 0.0f);
    }
    for (int i = tid; i < NAGT; i += 256) {
        float2 p = *(const float2*)(xabs + 2 * i);
        sx[i] = p.x; sy[i] = p.y;
    }
    __syncthreads();

    const float xn = sx[n] - 0.2f;
    const float yn = sy[n] - 0.2f;
    const int lane = tid & 31, w = tid >> 5;

    unsigned cnt = 0;
#pragma unroll
    for (int t = 0; t < 4; t++) {
        int m = w * 128 + t * 32 + lane;
        float dx = sx[m] - xn;
        float dy = sy[m] - yn;
        bool v = (m != n) && dx >= 0.0f && dx < 0.4f && dy >= 0.0f && dy < 0.4f;
        int cell = 0;
        if (v) {
            int cx = (int)floorf(dx * 20.0f);
            int cy = (int)floorf(dy * 20.0f);
            v = (cx >= 0) && (cx < 8) && (cy >= 0) && (cy < 8);
            cell = cx + cy * 8;
        }
        unsigned mask = __ballot_sync(0xffffffffu, v);
        if (v) {
            int pos = cnt + __popc(mask & ((1u << lane) - 1u));
            list[w * 128 + pos] = (unsigned short)((m << 6) | cell);
        }
        cnt += __popc(mask);
    }
    if (lane == 0) s_cnt[w] = cnt;
    __syncthreads();

    const int grp = tid >> 6;
    const int e   = tid & 63;
    float acc = 0.0f;
#pragma unroll
    for (int ws = grp * 2; ws < grp * 2 + 2; ws++) {
        int c = s_cnt[ws];
        for (int i = 0; i < c; i++) {
            unsigned v = list[ws * 128 + i];
            acc += g_Hs[(v >> 6) * 4096 + (v & 63) * 64 + e];
        }
    }
    red[grp][e] = acc;
    __syncthreads();
    if (tid < 64) {
        float sum = red[0][tid] + red[1][tid] + red[2][tid] + red[3][tid] + b_soc[tid];
        g_xin[n * 128 + 64 + tid] = fmaxf(sum, 0.0f);
    }
}

// ---------------- gatesA: xin @ Wih^T, grid=(16,4), 256 thr --------------
__global__ void __launch_bounds__(256) k_gatesA(const float* __restrict__ Wih) {
    __shared__ __align__(16) GSmem s;
    const int m0 = blockIdx.x * 64;
    const int j0 = blockIdx.y * 128;
    const int tid = threadIdx.x;
    const int tx = tid & 15, ty = tid >> 4;

    const float* Bw = Wih + j0 * 128;

    ull acc[4][4];
#pragma unroll
    for (int i = 0; i < 4; i++)
#pragma unroll
        for (int j = 0; j < 4; j++) acc[i][j] = 0ull;

#pragma unroll 1
    for (int kc = 0; kc < 4; kc++) {
        const int kb = kc * 32;
#pragma unroll
        for (int p = 0; p < 2; p++) {
            int idx = tid + p * 256;
            int k4 = idx & 7, m = idx >> 3;
            float4 v = *(const float4*)(g_xin + (m0 + m) * 128 + kb + k4 * 4);
            int base = m * 66 + k4 * 8;
            *(ull*)&s.As[base + 0] = dup2(v.x);
            *(ull*)&s.As[base + 2] = dup2(v.y);
            *(ull*)&s.As[base + 4] = dup2(v.z);
            *(ull*)&s.As[base + 6] = dup2(v.w);
        }
#pragma unroll
        for (int p = 0; p < 4; p++) {
            int idx = tid + p * 256;
            int k4 = idx & 7, c = idx >> 3;
            float4 v = *(const float4*)(Bw + c * 128 + kb + k4 * 4);
            s.Bs[(k4 * 4 + 0) * 130 + c] = v.x;
            s.Bs[(k4 * 4 + 1) * 130 + c] = v.y;
            s.Bs[(k4 * 4 + 2) * 130 + c] = v.z;
            s.Bs[(k4 * 4 + 3) * 130 + c] = v.w;
        }
        __syncthreads();
#pragma unroll 4
        for (int k = 0; k < 32; k++) {
            ull bb[4];
#pragma unroll
            for (int j = 0; j < 4; j++)
                bb[j] = *(const ull*)&s.Bs[k * 130 + 2 * tx + 32 * j];
#pragma unroll
            for (int i = 0; i < 4; i++) {
                ull a = *(const ull*)&s.As[(ty * 4 + i) * 66 + 2 * k];
#pragma unroll
                for (int j = 0; j < 4; j++) ffma2(acc[i][j], a, bb[j]);
            }
        }
        __syncthreads();
    }
#pragma unroll
    for (int i = 0; i < 4; i++) {
        int m = m0 + ty * 4 + i;
#pragma unroll
        for (int j = 0; j < 4; j++) {
            float2 v = unpack2(acc[i][j]);
            *(float2*)&g_gatesA[m * 512 + j0 + 2 * tx + 32 * j] = v;
        }
    }
}

// ---------------- Kernel D: fused LSTM elementwise + out GEMM (r10) ------
#define KD_WOT_PAD 121
#define KD_SMEM ((8 * 128 + 128 * KD_WOT_PAD) * 4)   // 66048 B

__global__ void __launch_bounds__(512) kD(const float* __restrict__ c0v,
                                          const float* __restrict__ b_ih,
                                          const float* __restrict__ b_hh,
                                          const float* __restrict__ Wout,
                                          const float* __restrict__ b_out,
                                          float* __restrict__ out) {
    extern __shared__ float sdynf[];
    float* Hn  = sdynf;                 // [8][128]
    float* WoT = sdynf + 8 * 128;       // [128][121]
    const int m0 = blockIdx.x * 8;
    const int tid = threadIdx.x;

#pragma unroll
    for (int p = 0; p < 2; p++) {
        int id = tid + p * 512;
        int r = id >> 7, k = id & 127;
        const float* ga = g_gatesA + (m0 + r) * 512;
        const float* gb = g_gatesB + (m0 + r) * 512;
        float iv = ga[k]       + gb[k]       + b_ih[k]       + b_hh[k];
        float fv = ga[128 + k] + gb[128 + k] + b_ih[128 + k] + b_hh[128 + k];
        float gv = ga[256 + k] + gb[256 + k] + b_ih[256 + k] + b_hh[256 + k];
        float ov = ga[384 + k] + gb[384 + k] + b_ih[384 + k] + b_hh[384 + k];
        float si = sigmoid_ap(iv);
        float sf = sigmoid_ap(fv);
        float so = sigmoid_ap(ov);
        float c  = sf * c0v[(m0 + r) * 128 + k] + si * tanh_ap(gv);
        Hn[r * 128 + k] = so * tanh_ap(c);
    }

    for (int i = tid; i < 120 * 32; i += 512) {
        int c = i >> 5, k4 = i & 31;
        float4 v = *(const float4*)(Wout + c * 128 + k4 * 4);
        WoT[(k4 * 4 + 0) * KD_WOT_PAD + c] = v.x;
        WoT[(k4 * 4 + 1) * KD_WOT_PAD + c] = v.y;
        WoT[(k4 * 4 + 2) * KD_WOT_PAD + c] = v.z;
        WoT[(k4 * 4 + 3) * KD_WOT_PAD + c] = v.w;
    }
    __syncthreads();

    const int ty = tid >> 7;            // 0..3 -> rows ty*2, ty*2+1
    const int tx = tid & 127;           // col (active < 120)
    if (tx < 120) {
        const float* h0r = Hn + (ty * 2 + 0) * 128;
        const float* h1r = Hn + (ty * 2 + 1) * 128;
        float acc0 = 0.0f, acc1 = 0.0f;
#pragma unroll 8
        for (int k = 0; k < 128; k++) {
            float b = WoT[k * KD_WOT_PAD + tx];
            acc0 = fmaf(h0r[k], b, acc0);
            acc1 = fmaf(h1r[k], b, acc1);
        }
        float bo = b_out[tx];
        int cdiv = tx / 20, cmod = tx % 20;
        int n0 = m0 + ty * 2;
        out[cdiv * (NAGT * NMIX) + n0 * NMIX + cmod]       = acc0 + bo;
        out[cdiv * (NAGT * NMIX) + (n0 + 1) * NMIX + cmod] = acc1 + bo;
    }
}

// ---------------- launch ----------------
extern "C" void kernel_launch(void* const* d_in, const int* in_sizes, int n_in,
                              void* d_out, int out_size) {
    const float* xoff  = (const float*)d_in[0];
    const float* xabs  = (const float*)d_in[1];
    const float* h0    = (const float*)d_in[2];
    const float* c0    = (const float*)d_in[3];
    const float* W_emb = (const float*)d_in[4];
    const float* b_emb = (const float*)d_in[5];
    const float* W_soc = (const float*)d_in[6];
    const float* b_soc = (const float*)d_in[7];
    const float* W_ih  = (const float*)d_in[8];
    const float* W_hh  = (const float*)d_in[9];
    const float* b_ih  = (const float*)d_in[10];
    const float* b_hh  = (const float*)d_in[11];
    const float* W_out = (const float*)d_in[12];
    const float* b_out = (const float*)d_in[13];
    float* out = (float*)d_out;

    cudaFuncSetAttribute(kA, cudaFuncAttributeMaxDynamicSharedMemorySize, HS_SMEM);
    cudaFuncSetAttribute(kD, cudaFuncAttributeMaxDynamicSharedMemorySize, KD_SMEM);

    kA<<<128, 512, HS_SMEM>>>(h0, W_soc, W_hh);
    k_pool<<<NAGT, 256>>>(xabs, b_soc, xoff, W_emb, b_emb);
    k_gatesA<<<dim3(16, 4), 256>>>(W_ih);
    kD<<<128, 512, KD_SMEM>>>(c0, b_ih, b_hh, W_out, b_out, out);
}